// round 1
// baseline (speedup 1.0000x reference)
#include <cuda_runtime.h>
#include <math.h>

#define Nn 50000
#define Ee 800000
#define Hh 128

// ---------------- scratch (device globals; no allocation allowed) -----------
__device__ float g_x [(size_t)Nn*Hh];
__device__ float g_xa[(size_t)Nn*Hh];
__device__ float g_xb[(size_t)Nn*Hh];
__device__ float g_agg[(size_t)Nn*Hh];
__device__ float g_ea[(size_t)Ee*Hh];
__device__ float g_red[Hh];

// Tile scheme shared by all GEMM-ish kernels:
// 256 threads = 8 warps; block handles 64 rows; warp w owns rows w*8..w*8+7;
// lane owns 4 consecutive output columns (lane*4).  acc[8][4] per thread.

// ---------------- node encoder: x = nf[N,64] @ W[64,128] + b ----------------
__global__ void enc_nodes_kernel(const float* __restrict__ nf,
                                 const float* __restrict__ W,
                                 const float* __restrict__ b) {
    extern __shared__ float sm[];
    float* sIn = sm;            // 64x64
    float* sW  = sm + 64*64;    // 64x128
    int tid = threadIdx.x, warp = tid >> 5, lane = tid & 31;
    int rb = blockIdx.x * 64;
#pragma unroll
    for (int it = 0; it < 4; ++it) {
        int idx = tid + it*256;            // 1024 float4s
        int row = idx >> 4, c4 = idx & 15;
        int r = rb + row; if (r >= Nn) r = Nn - 1;
        ((float4*)sIn)[idx] = ((const float4*)(nf + (size_t)r*64))[c4];
    }
#pragma unroll
    for (int it = 0; it < 8; ++it) {
        int idx = tid + it*256;            // 2048 float4s
        ((float4*)sW)[idx] = ((const float4*)W)[idx];
    }
    __syncthreads();
    float acc[8][4];
#pragma unroll
    for (int i = 0; i < 8; ++i) { acc[i][0]=acc[i][1]=acc[i][2]=acc[i][3]=0.f; }
#pragma unroll 8
    for (int k = 0; k < 64; ++k) {
        float4 w = ((float4*)(sW + k*128))[lane];
#pragma unroll
        for (int i = 0; i < 8; ++i) {
            float a = sIn[(warp*8 + i)*64 + k];
            acc[i][0] = fmaf(a, w.x, acc[i][0]);
            acc[i][1] = fmaf(a, w.y, acc[i][1]);
            acc[i][2] = fmaf(a, w.z, acc[i][2]);
            acc[i][3] = fmaf(a, w.w, acc[i][3]);
        }
    }
    float4 bb = ((const float4*)b)[lane];
#pragma unroll
    for (int i = 0; i < 8; ++i) {
        int r = rb + warp*8 + i;
        if (r < Nn) {
            float4 v = make_float4(acc[i][0]+bb.x, acc[i][1]+bb.y,
                                   acc[i][2]+bb.z, acc[i][3]+bb.w);
            ((float4*)(g_x + (size_t)r*128))[lane] = v;
        }
    }
}

// ---------------- edge encoder: ea = ef[E,32] @ W[32,128] + b ---------------
__global__ void enc_edges_kernel(const float* __restrict__ ef,
                                 const float* __restrict__ W,
                                 const float* __restrict__ b) {
    extern __shared__ float sm[];
    float* sIn = sm;            // 64x32
    float* sW  = sm + 64*32;    // 32x128
    int tid = threadIdx.x, warp = tid >> 5, lane = tid & 31;
    size_t eb = (size_t)blockIdx.x * 64;
#pragma unroll
    for (int it = 0; it < 2; ++it) {
        int idx = tid + it*256;            // 512 float4s
        ((float4*)sIn)[idx] = ((const float4*)(ef + eb*32))[idx];
    }
#pragma unroll
    for (int it = 0; it < 4; ++it) {
        int idx = tid + it*256;            // 1024 float4s
        ((float4*)sW)[idx] = ((const float4*)W)[idx];
    }
    __syncthreads();
    float acc[8][4];
#pragma unroll
    for (int i = 0; i < 8; ++i) { acc[i][0]=acc[i][1]=acc[i][2]=acc[i][3]=0.f; }
#pragma unroll 8
    for (int k = 0; k < 32; ++k) {
        float4 w = ((float4*)(sW + k*128))[lane];
#pragma unroll
        for (int i = 0; i < 8; ++i) {
            float a = sIn[(warp*8 + i)*32 + k];
            acc[i][0] = fmaf(a, w.x, acc[i][0]);
            acc[i][1] = fmaf(a, w.y, acc[i][1]);
            acc[i][2] = fmaf(a, w.z, acc[i][2]);
            acc[i][3] = fmaf(a, w.w, acc[i][3]);
        }
    }
    float4 bb = ((const float4*)b)[lane];
#pragma unroll
    for (int i = 0; i < 8; ++i) {
        size_t e = eb + warp*8 + i;
        float4 v = make_float4(acc[i][0]+bb.x, acc[i][1]+bb.y,
                               acc[i][2]+bb.z, acc[i][3]+bb.w);
        ((float4*)(g_ea + e*128))[lane] = v;
    }
}

// --------- per-layer node precompute: xa = x@W1a + cong*wc + b1 ; xb = x@W1b
__global__ void node_pre_kernel(const float* __restrict__ cong,
                                const float* __restrict__ w1l,  // [385,128]
                                const float* __restrict__ b1) {
    extern __shared__ float sm[];
    float* sIn = sm;            // 64x128 (x tile)
    float* sW  = sm + 64*128;   // 64x128 chunk
    int tid = threadIdx.x, warp = tid >> 5, lane = tid & 31;
    int rb = blockIdx.x * 64;
#pragma unroll
    for (int it = 0; it < 8; ++it) {
        int idx = tid + it*256;            // 2048 float4s
        int row = idx >> 5, c4 = idx & 31;
        int r = rb + row; if (r >= Nn) r = Nn - 1;
        ((float4*)sIn)[idx] = ((const float4*)(g_x + (size_t)r*128))[c4];
    }
    float acc[8][4];
#pragma unroll
    for (int i = 0; i < 8; ++i) { acc[i][0]=acc[i][1]=acc[i][2]=acc[i][3]=0.f; }
    // GEMM A: rows 0..127 of w1l
    for (int kc = 0; kc < 128; kc += 64) {
        __syncthreads();
#pragma unroll
        for (int it = 0; it < 8; ++it) {
            int idx = tid + it*256;
            ((float4*)sW)[idx] = ((const float4*)(w1l + (size_t)kc*128))[idx];
        }
        __syncthreads();
#pragma unroll 8
        for (int k = 0; k < 64; ++k) {
            float4 w = ((float4*)(sW + k*128))[lane];
#pragma unroll
            for (int i = 0; i < 8; ++i) {
                float a = sIn[(warp*8 + i)*128 + kc + k];
                acc[i][0] = fmaf(a, w.x, acc[i][0]);
                acc[i][1] = fmaf(a, w.y, acc[i][1]);
                acc[i][2] = fmaf(a, w.z, acc[i][2]);
                acc[i][3] = fmaf(a, w.w, acc[i][3]);
            }
        }
    }
    float4 wc = ((const float4*)(w1l + (size_t)384*128))[lane];
    float4 b4 = ((const float4*)b1)[lane];
#pragma unroll
    for (int i = 0; i < 8; ++i) {
        int r = rb + warp*8 + i;
        if (r < Nn) {
            float c = cong[r];
            float4 v = make_float4(acc[i][0] + c*wc.x + b4.x,
                                   acc[i][1] + c*wc.y + b4.y,
                                   acc[i][2] + c*wc.z + b4.z,
                                   acc[i][3] + c*wc.w + b4.w);
            ((float4*)(g_xa + (size_t)r*128))[lane] = v;
        }
        acc[i][0]=acc[i][1]=acc[i][2]=acc[i][3]=0.f;
    }
    // GEMM B: rows 128..255 of w1l
    for (int kc = 0; kc < 128; kc += 64) {
        __syncthreads();
#pragma unroll
        for (int it = 0; it < 8; ++it) {
            int idx = tid + it*256;
            ((float4*)sW)[idx] = ((const float4*)(w1l + (size_t)(128+kc)*128))[idx];
        }
        __syncthreads();
#pragma unroll 8
        for (int k = 0; k < 64; ++k) {
            float4 w = ((float4*)(sW + k*128))[lane];
#pragma unroll
            for (int i = 0; i < 8; ++i) {
                float a = sIn[(warp*8 + i)*128 + kc + k];
                acc[i][0] = fmaf(a, w.x, acc[i][0]);
                acc[i][1] = fmaf(a, w.y, acc[i][1]);
                acc[i][2] = fmaf(a, w.z, acc[i][2]);
                acc[i][3] = fmaf(a, w.w, acc[i][3]);
            }
        }
    }
#pragma unroll
    for (int i = 0; i < 8; ++i) {
        int r = rb + warp*8 + i;
        if (r < Nn) {
            float4 v = make_float4(acc[i][0], acc[i][1], acc[i][2], acc[i][3]);
            ((float4*)(g_xb + (size_t)r*128))[lane] = v;
        }
    }
}

// ---------------- zero helpers ----------------------------------------------
__global__ void zero_agg_kernel() {
    size_t i = (size_t)blockIdx.x * blockDim.x + threadIdx.x;
    size_t n = (size_t)Nn * 128;
    if (i < n) g_agg[i] = 0.f;
}
__global__ void zero_red_kernel() { if (threadIdx.x < 128) g_red[threadIdx.x] = 0.f; }

// ------- edge kernel: h1 = relu(ea@W1e + xa[src] + xb[dst]); m = h1@W2 + b2;
// ------- agg[dst] += m  (fused double GEMM + gather + scatter) --------------
__global__ void edge_kernel(const int* __restrict__ eidx,
                            const float* __restrict__ W1e,  // [128,128]
                            const float* __restrict__ W2,   // [128,128]
                            const float* __restrict__ b2) {
    extern __shared__ float sm[];
    float* sIn = sm;            // 64x128 : ea tile, then h1 tile
    float* sW  = sm + 64*128;   // 64x128 weight chunk
    int tid = threadIdx.x, warp = tid >> 5, lane = tid & 31;
    size_t eb = (size_t)blockIdx.x * 64;
#pragma unroll
    for (int it = 0; it < 8; ++it) {
        int idx = tid + it*256;
        ((float4*)sIn)[idx] = ((const float4*)(g_ea + eb*128))[idx];
    }
    int se[8], de[8];
#pragma unroll
    for (int i = 0; i < 8; ++i) {
        size_t e = eb + (size_t)warp*8 + i;
        se[i] = eidx[e];
        de[i] = eidx[(size_t)Ee + e];
    }
    float acc[8][4];
#pragma unroll
    for (int i = 0; i < 8; ++i) { acc[i][0]=acc[i][1]=acc[i][2]=acc[i][3]=0.f; }
    // GEMM1: ea @ W1e
    for (int kc = 0; kc < 128; kc += 64) {
        __syncthreads();
#pragma unroll
        for (int it = 0; it < 8; ++it) {
            int idx = tid + it*256;
            ((float4*)sW)[idx] = ((const float4*)(W1e + (size_t)kc*128))[idx];
        }
        __syncthreads();
#pragma unroll 8
        for (int k = 0; k < 64; ++k) {
            float4 w = ((float4*)(sW + k*128))[lane];
#pragma unroll
            for (int i = 0; i < 8; ++i) {
                float a = sIn[(warp*8 + i)*128 + kc + k];
                acc[i][0] = fmaf(a, w.x, acc[i][0]);
                acc[i][1] = fmaf(a, w.y, acc[i][1]);
                acc[i][2] = fmaf(a, w.z, acc[i][2]);
                acc[i][3] = fmaf(a, w.w, acc[i][3]);
            }
        }
    }
    __syncthreads();   // everyone done reading ea tile
#pragma unroll
    for (int i = 0; i < 8; ++i) {
        float4 ga = ((const float4*)(g_xa + (size_t)se[i]*128))[lane];
        float4 gb = ((const float4*)(g_xb + (size_t)de[i]*128))[lane];
        float4 h;
        h.x = fmaxf(acc[i][0] + ga.x + gb.x, 0.f);
        h.y = fmaxf(acc[i][1] + ga.y + gb.y, 0.f);
        h.z = fmaxf(acc[i][2] + ga.z + gb.z, 0.f);
        h.w = fmaxf(acc[i][3] + ga.w + gb.w, 0.f);
        ((float4*)(sIn + (warp*8 + i)*128))[lane] = h;
        acc[i][0]=acc[i][1]=acc[i][2]=acc[i][3]=0.f;
    }
    // GEMM2: h1 @ W2
    for (int kc = 0; kc < 128; kc += 64) {
        __syncthreads();
#pragma unroll
        for (int it = 0; it < 8; ++it) {
            int idx = tid + it*256;
            ((float4*)sW)[idx] = ((const float4*)(W2 + (size_t)kc*128))[idx];
        }
        __syncthreads();
#pragma unroll 8
        for (int k = 0; k < 64; ++k) {
            float4 w = ((float4*)(sW + k*128))[lane];
#pragma unroll
            for (int i = 0; i < 8; ++i) {
                float a = sIn[(warp*8 + i)*128 + kc + k];
                acc[i][0] = fmaf(a, w.x, acc[i][0]);
                acc[i][1] = fmaf(a, w.y, acc[i][1]);
                acc[i][2] = fmaf(a, w.z, acc[i][2]);
                acc[i][3] = fmaf(a, w.w, acc[i][3]);
            }
        }
    }
    float4 bb = ((const float4*)b2)[lane];
#pragma unroll
    for (int i = 0; i < 8; ++i) {
        float* dp = g_agg + (size_t)de[i]*128 + lane*4;
        atomicAdd(dp + 0, acc[i][0] + bb.x);
        atomicAdd(dp + 1, acc[i][1] + bb.y);
        atomicAdd(dp + 2, acc[i][2] + bb.z);
        atomicAdd(dp + 3, acc[i][3] + bb.w);
    }
}

// ------- update: x = LN(x + MLP([x, agg])) ----------------------------------
__global__ void update_kernel(const float* __restrict__ U1,   // [256,128]
                              const float* __restrict__ ub1,
                              const float* __restrict__ U2,   // [128,128]
                              const float* __restrict__ ub2,
                              const float* __restrict__ lw,
                              const float* __restrict__ lb) {
    extern __shared__ float sm[];
    float* sW   = sm;                 // 64x128
    float* sInC = sm + 64*128;        // 64x64
    float* sAux = sm + 64*128 + 64*64;// 64x128
    int tid = threadIdx.x, warp = tid >> 5, lane = tid & 31;
    int rb = blockIdx.x * 64;
    float acc[8][4];
#pragma unroll
    for (int i = 0; i < 8; ++i) { acc[i][0]=acc[i][1]=acc[i][2]=acc[i][3]=0.f; }
    for (int kc = 0; kc < 256; kc += 64) {
        __syncthreads();
        const float* src = (kc < 128) ? (g_x + kc) : (g_agg + (kc - 128));
#pragma unroll
        for (int it = 0; it < 4; ++it) {
            int idx = tid + it*256;           // 1024 float4s
            int row = idx >> 4, c4 = idx & 15;
            int r = rb + row; if (r >= Nn) r = Nn - 1;
            ((float4*)sInC)[idx] = ((const float4*)(src + (size_t)r*128))[c4];
        }
#pragma unroll
        for (int it = 0; it < 8; ++it) {
            int idx = tid + it*256;
            ((float4*)sW)[idx] = ((const float4*)(U1 + (size_t)kc*128))[idx];
        }
        __syncthreads();
#pragma unroll 8
        for (int k = 0; k < 64; ++k) {
            float4 w = ((float4*)(sW + k*128))[lane];
#pragma unroll
            for (int i = 0; i < 8; ++i) {
                float a = sInC[(warp*8 + i)*64 + k];
                acc[i][0] = fmaf(a, w.x, acc[i][0]);
                acc[i][1] = fmaf(a, w.y, acc[i][1]);
                acc[i][2] = fmaf(a, w.z, acc[i][2]);
                acc[i][3] = fmaf(a, w.w, acc[i][3]);
            }
        }
    }
    float4 b14 = ((const float4*)ub1)[lane];
    __syncthreads();
#pragma unroll
    for (int i = 0; i < 8; ++i) {
        float4 h;
        h.x = fmaxf(acc[i][0] + b14.x, 0.f);
        h.y = fmaxf(acc[i][1] + b14.y, 0.f);
        h.z = fmaxf(acc[i][2] + b14.z, 0.f);
        h.w = fmaxf(acc[i][3] + b14.w, 0.f);
        ((float4*)(sAux + (warp*8 + i)*128))[lane] = h;
        acc[i][0]=acc[i][1]=acc[i][2]=acc[i][3]=0.f;
    }
    for (int kc = 0; kc < 128; kc += 64) {
        __syncthreads();
#pragma unroll
        for (int it = 0; it < 8; ++it) {
            int idx = tid + it*256;
            ((float4*)sW)[idx] = ((const float4*)(U2 + (size_t)kc*128))[idx];
        }
        __syncthreads();
#pragma unroll 8
        for (int k = 0; k < 64; ++k) {
            float4 w = ((float4*)(sW + k*128))[lane];
#pragma unroll
            for (int i = 0; i < 8; ++i) {
                float a = sAux[(warp*8 + i)*128 + kc + k];
                acc[i][0] = fmaf(a, w.x, acc[i][0]);
                acc[i][1] = fmaf(a, w.y, acc[i][1]);
                acc[i][2] = fmaf(a, w.z, acc[i][2]);
                acc[i][3] = fmaf(a, w.w, acc[i][3]);
            }
        }
    }
    float4 b24 = ((const float4*)ub2)[lane];
    __syncthreads();   // all GEMM2 reads of sAux done before overwrite
#pragma unroll
    for (int i = 0; i < 8; ++i) {
        int r = rb + warp*8 + i; int rc = (r >= Nn) ? (Nn - 1) : r;
        float4 xr = ((const float4*)(g_x + (size_t)rc*128))[lane];
        float4 y = make_float4(xr.x + acc[i][0] + b24.x,
                               xr.y + acc[i][1] + b24.y,
                               xr.z + acc[i][2] + b24.z,
                               xr.w + acc[i][3] + b24.w);
        ((float4*)(sAux + (warp*8 + i)*128))[lane] = y;
    }
    __syncthreads();
    float4 lw4 = ((const float4*)lw)[lane];
    float4 lb4 = ((const float4*)lb)[lane];
#pragma unroll
    for (int i = 0; i < 8; ++i) {
        int row = warp*8 + i; int r = rb + row;
        float4 v = ((float4*)(sAux + row*128))[lane];
        float s = v.x + v.y + v.z + v.w;
#pragma unroll
        for (int o = 16; o > 0; o >>= 1) s += __shfl_xor_sync(0xffffffffu, s, o);
        float mu = s * (1.f/128.f);
        float dx = v.x - mu, dy = v.y - mu, dz = v.z - mu, dw = v.w - mu;
        float q = dx*dx + dy*dy + dz*dz + dw*dw;
#pragma unroll
        for (int o = 16; o > 0; o >>= 1) q += __shfl_xor_sync(0xffffffffu, q, o);
        float rstd = rsqrtf(q * (1.f/128.f) + 1e-5f);
        if (r < Nn) {
            float4 o4 = make_float4(dx*rstd*lw4.x + lb4.x,
                                    dy*rstd*lw4.y + lb4.y,
                                    dz*rstd*lw4.z + lb4.z,
                                    dw*rstd*lw4.w + lb4.w);
            ((float4*)(g_x + (size_t)r*128))[lane] = o4;
        }
    }
}

// ---------------- column-sum reduce over nodes ------------------------------
__global__ void reduce_kernel() {
    int j = threadIdx.x;       // 128 threads
    int chunk = (Nn + gridDim.x - 1) / gridDim.x;
    int r0 = blockIdx.x * chunk;
    int r1 = r0 + chunk; if (r1 > Nn) r1 = Nn;
    float s = 0.f;
    for (int r = r0; r < r1; ++r) s += g_x[(size_t)r*128 + j];
    atomicAdd(&g_red[j], s);
}

// ---------------- readout head (single block, 128 threads) ------------------
__global__ void final_kernel(const void* __restrict__ maskp,
                             const float* __restrict__ uw1, const float* __restrict__ ub1f,
                             const float* __restrict__ uw2, const float* __restrict__ ub2f,
                             const float* __restrict__ rw1, const float* __restrict__ rb1,
                             const float* __restrict__ rw2, const float* __restrict__ rb2,
                             const float* __restrict__ rw3, const float* __restrict__ rb3,
                             float* __restrict__ out) {
    __shared__ float sge[128], s1[128], s2[128];
    __shared__ int c1s, c2s;
    __shared__ float sufs;
    int j = threadIdx.x;
    if (j == 0) { c1s = 0; c2s = 0; sufs = 0.f; }
    __syncthreads();
    // dtype sniff for the bool mask: uint8 / int32 / float32 all hold 0-or-1
    // values; byte pattern over the first Nn bytes disambiguates safely.
    const unsigned char* mb = (const unsigned char*)maskp;
    int c1 = 0, c2 = 0;
    for (int i = j; i < Nn; i += 128) {
        unsigned char v = mb[i];
        if (v) { if ((i & 3) == 0) c1++; else c2++; }
    }
    atomicAdd(&c1s, c1); atomicAdd(&c2s, c2);
    __syncthreads();
    float s = 0.f;
    if (c2s == 0) {                 // int32 0/1
        const int* mi = (const int*)maskp;
        for (int i = j; i < Nn; i += 128) s += (mi[i] != 0) ? 1.f : 0.f;
    } else if (c1s == 0) {          // float32 0.0/1.0
        const float* mf = (const float*)maskp;
        for (int i = j; i < Nn; i += 128) s += mf[i];
    } else {                        // uint8 bool
        for (int i = j; i < Nn; i += 128) s += mb[i] ? 1.f : 0.f;
    }
    atomicAdd(&sufs, s);
    sge[j] = g_red[j] * (1.f/(float)Nn);
    __syncthreads();
    float uf = sufs * (1.f/(float)Nn);
    s1[j] = fmaxf(uf * uw1[j] + ub1f[j], 0.f);
    __syncthreads();
    float t = ub2f[j];
    for (int k = 0; k < 128; ++k) t = fmaf(s1[k], uw2[k*128 + j], t);
    s2[j] = t;
    __syncthreads();
    float h = rb1[j];
    for (int k = 0; k < 128; ++k) h = fmaf(sge[k], rw1[k*128 + j], h);
    for (int k = 0; k < 128; ++k) h = fmaf(s2[k], rw1[(128 + k)*128 + j], h);
    s1[j] = fmaxf(h, 0.f);
    __syncthreads();
    if (j < 64) {
        float g = rb2[j];
        for (int k = 0; k < 128; ++k) g = fmaf(s1[k], rw2[k*64 + j], g);
        s2[j] = fmaxf(g, 0.f);
    }
    __syncthreads();
    if (j == 0) {
        float o = rb3[0];
        for (int k = 0; k < 64; ++k) o = fmaf(s2[k], rw3[k], o);
        out[0] = 1.f / (1.f + expf(-o));
    }
}

// ---------------- launch -----------------------------------------------------
extern "C" void kernel_launch(void* const* d_in, const int* in_sizes, int n_in,
                              void* d_out, int out_size) {
    const float* nf        = (const float*)d_in[0];
    const float* ef        = (const float*)d_in[1];
    const float* cong      = (const float*)d_in[2];
    const int*   eidx      = (const int*)d_in[3];
    const void*  mask      = d_in[4];
    const float* enc_node_w = (const float*)d_in[5];
    const float* enc_node_b = (const float*)d_in[6];
    const float* enc_edge_w = (const float*)d_in[7];
    const float* enc_edge_b = (const float*)d_in[8];
    const float* msg_w1 = (const float*)d_in[9];
    const float* msg_b1 = (const float*)d_in[10];
    const float* msg_w2 = (const float*)d_in[11];
    const float* msg_b2 = (const float*)d_in[12];
    const float* upd_w1 = (const float*)d_in[13];
    const float* upd_b1 = (const float*)d_in[14];
    const float* upd_w2 = (const float*)d_in[15];
    const float* upd_b2 = (const float*)d_in[16];
    const float* ln_w   = (const float*)d_in[17];
    const float* ln_b   = (const float*)d_in[18];
    const float* unr_w1 = (const float*)d_in[19];
    const float* unr_b1 = (const float*)d_in[20];
    const float* unr_w2 = (const float*)d_in[21];
    const float* unr_b2 = (const float*)d_in[22];
    const float* ro_w1  = (const float*)d_in[23];
    const float* ro_b1  = (const float*)d_in[24];
    const float* ro_w2  = (const float*)d_in[25];
    const float* ro_b2  = (const float*)d_in[26];
    const float* ro_w3  = (const float*)d_in[27];
    const float* ro_b3  = (const float*)d_in[28];
    float* out = (float*)d_out;

    const int SM_ENC_N = (64*64 + 64*128) * 4;          // 48 KB
    const int SM_ENC_E = (64*32 + 32*128) * 4;          // 24 KB
    const int SM_NP    = (64*128 + 64*128) * 4;         // 64 KB
    const int SM_EDGE  = SM_NP;                          // 64 KB
    const int SM_UPD   = (64*128 + 64*64 + 64*128) * 4; // 80 KB

    cudaFuncSetAttribute(enc_nodes_kernel, cudaFuncAttributeMaxDynamicSharedMemorySize, SM_ENC_N);
    cudaFuncSetAttribute(node_pre_kernel,  cudaFuncAttributeMaxDynamicSharedMemorySize, SM_NP);
    cudaFuncSetAttribute(edge_kernel,      cudaFuncAttributeMaxDynamicSharedMemorySize, SM_EDGE);
    cudaFuncSetAttribute(update_kernel,    cudaFuncAttributeMaxDynamicSharedMemorySize, SM_UPD);

    const int NODE_BLOCKS = (Nn + 63) / 64;   // 782
    const int EDGE_BLOCKS = Ee / 64;          // 12500

    enc_nodes_kernel<<<NODE_BLOCKS, 256, SM_ENC_N>>>(nf, enc_node_w, enc_node_b);
    enc_edges_kernel<<<EDGE_BLOCKS, 256, SM_ENC_E>>>(ef, enc_edge_w, enc_edge_b);

    for (int l = 0; l < 4; ++l) {
        node_pre_kernel<<<NODE_BLOCKS, 256, SM_NP>>>(
            cong, msg_w1 + (size_t)l*385*128, msg_b1 + (size_t)l*128);
        zero_agg_kernel<<<(Nn*128 + 1023)/1024, 1024>>>();
        edge_kernel<<<EDGE_BLOCKS, 256, SM_EDGE>>>(
            eidx,
            msg_w1 + ((size_t)l*385 + 256)*128,
            msg_w2 + (size_t)l*128*128,
            msg_b2 + (size_t)l*128);
        update_kernel<<<NODE_BLOCKS, 256, SM_UPD>>>(
            upd_w1 + (size_t)l*256*128, upd_b1 + (size_t)l*128,
            upd_w2 + (size_t)l*128*128, upd_b2 + (size_t)l*128,
            ln_w + (size_t)l*128, ln_b + (size_t)l*128);
    }

    zero_red_kernel<<<1, 128>>>();
    reduce_kernel<<<250, 128>>>();
    final_kernel<<<1, 128>>>(mask, unr_w1, unr_b1, unr_w2, unr_b2,
                             ro_w1, ro_b1, ro_w2, ro_b2, ro_w3, ro_b3, out);
}

// round 3
// speedup vs baseline: 1.7486x; 1.7486x over previous
#include <cuda_runtime.h>
#include <cuda_bf16.h>
#include <math.h>

#define Nn 50000
#define Ee 800000
#define LDS 136   // smem row stride in bf16 elems (conflict-free padding)

// ---------------- scratch (device globals; no allocation allowed) -----------
__device__ float          g_x  [(size_t)Nn*128];
__device__ __nv_bfloat16  g_xbf[(size_t)Nn*128];
__device__ __nv_bfloat16  g_xa [(size_t)Nn*128];
__device__ __nv_bfloat16  g_xb [(size_t)Nn*128];
__device__ float          g_agg[(size_t)Nn*128];
__device__ __nv_bfloat16  g_ea [(size_t)Ee*128];
__device__ float          g_red[128];

// ---------------- mma helpers ------------------------------------------------
__device__ __forceinline__ unsigned sptr(const void* p){
    return (unsigned)__cvta_generic_to_shared((void*)p);
}
__device__ __forceinline__ void ldsmA(unsigned a, unsigned &r0, unsigned &r1,
                                      unsigned &r2, unsigned &r3){
    asm volatile("ldmatrix.sync.aligned.m8n8.x4.shared.b16 {%0,%1,%2,%3},[%4];"
        : "=r"(r0),"=r"(r1),"=r"(r2),"=r"(r3) : "r"(a));
}
__device__ __forceinline__ void ldsmBT(unsigned a, unsigned &r0, unsigned &r1,
                                       unsigned &r2, unsigned &r3){
    asm volatile("ldmatrix.sync.aligned.m8n8.x4.trans.shared.b16 {%0,%1,%2,%3},[%4];"
        : "=r"(r0),"=r"(r1),"=r"(r2),"=r"(r3) : "r"(a));
}
__device__ __forceinline__ void mma_bf16(float* c, unsigned a0, unsigned a1,
                                         unsigned a2, unsigned a3,
                                         unsigned b0, unsigned b1){
    asm volatile("mma.sync.aligned.m16n8k16.row.col.f32.bf16.bf16.f32 "
        "{%0,%1,%2,%3},{%4,%5,%6,%7},{%8,%9},{%0,%1,%2,%3};"
        : "+f"(c[0]),"+f"(c[1]),"+f"(c[2]),"+f"(c[3])
        : "r"(a0),"r"(a1),"r"(a2),"r"(a3),"r"(b0),"r"(b1));
}
__device__ __forceinline__ unsigned packbf(float a, float b){
    __nv_bfloat162 h = __floats2bfloat162_rn(a, b);
    return *(unsigned*)&h;
}
__device__ __forceinline__ float2 unpackbf(unsigned u){
    __nv_bfloat162 h = *(__nv_bfloat162*)&u;
    return make_float2(__bfloat162float(h.x), __bfloat162float(h.y));
}

// Load fp32 weight [128][128] into SMEM bf16 [128][LDS].
// part 0: hi = bf16(w); part 1: lo = bf16(w - float(hi)).
__device__ __forceinline__ void load_w_split(const float* __restrict__ W,
                                             __nv_bfloat16* sW, int part, int tid){
#pragma unroll
    for (int it = 0; it < 16; ++it){
        int idx = tid + it*256;
        int row = idx >> 5, c4 = idx & 31;
        float4 w = __ldg((const float4*)W + idx);
        float4 v = w;
        if (part){
            v.x = w.x - __bfloat162float(__float2bfloat16(w.x));
            v.y = w.y - __bfloat162float(__float2bfloat16(w.y));
            v.z = w.z - __bfloat162float(__float2bfloat16(w.z));
            v.w = w.w - __bfloat162float(__float2bfloat16(w.w));
        }
        *(uint2*)(sW + row*LDS + c4*4) = make_uint2(packbf(v.x, v.y), packbf(v.z, v.w));
    }
}

// Warp-level 16x128 @ 128x128 mma accumulate. Warp w owns rows w*16..w*16+15.
__device__ __forceinline__ void mma_gemm128(const __nv_bfloat16* sA,
                                            const __nv_bfloat16* sW,
                                            float acc[16][4], int warp, int lane){
    unsigned aB = sptr(sA + (warp*16 + (lane & 15))*LDS + (lane >> 4)*8);
    unsigned bB = sptr(sW + (lane & 15)*LDS + (lane >> 4)*8);
#pragma unroll
    for (int kk = 0; kk < 8; ++kk){
        unsigned a0,a1,a2,a3;
        ldsmA(aB + kk*32, a0,a1,a2,a3);
#pragma unroll
        for (int jp = 0; jp < 8; ++jp){
            unsigned b0,b1,b2,b3;
            ldsmBT(bB + kk*(16*LDS*2) + jp*32, b0,b1,b2,b3);
            mma_bf16(acc[2*jp],   a0,a1,a2,a3, b0,b1);
            mma_bf16(acc[2*jp+1], a0,a1,a2,a3, b2,b3);
        }
    }
}

// ---------------- node encoder: x = nf[N,64] @ W[64,128] + b (fp32 FFMA) ----
__global__ void enc_nodes_kernel(const float* __restrict__ nf,
                                 const float* __restrict__ W,
                                 const float* __restrict__ b) {
    extern __shared__ float sm[];
    float* sIn = sm;            // 64x64
    float* sW  = sm + 64*64;    // 64x128
    int tid = threadIdx.x, warp = tid >> 5, lane = tid & 31;
    int rb = blockIdx.x * 64;
#pragma unroll
    for (int it = 0; it < 4; ++it) {
        int idx = tid + it*256;
        int row = idx >> 4, c4 = idx & 15;
        int r = rb + row; if (r >= Nn) r = Nn - 1;
        ((float4*)sIn)[idx] = ((const float4*)(nf + (size_t)r*64))[c4];
    }
#pragma unroll
    for (int it = 0; it < 8; ++it) {
        int idx = tid + it*256;
        ((float4*)sW)[idx] = ((const float4*)W)[idx];
    }
    __syncthreads();
    float acc[8][4];
#pragma unroll
    for (int i = 0; i < 8; ++i) { acc[i][0]=acc[i][1]=acc[i][2]=acc[i][3]=0.f; }
#pragma unroll 8
    for (int k = 0; k < 64; ++k) {
        float4 w = ((float4*)(sW + k*128))[lane];
#pragma unroll
        for (int i = 0; i < 8; ++i) {
            float a = sIn[(warp*8 + i)*64 + k];
            acc[i][0] = fmaf(a, w.x, acc[i][0]);
            acc[i][1] = fmaf(a, w.y, acc[i][1]);
            acc[i][2] = fmaf(a, w.z, acc[i][2]);
            acc[i][3] = fmaf(a, w.w, acc[i][3]);
        }
    }
    float4 bb = ((const float4*)b)[lane];
#pragma unroll
    for (int i = 0; i < 8; ++i) {
        int r = rb + warp*8 + i;
        if (r < Nn) {
            float4 v = make_float4(acc[i][0]+bb.x, acc[i][1]+bb.y,
                                   acc[i][2]+bb.z, acc[i][3]+bb.w);
            ((float4*)(g_x + (size_t)r*128))[lane] = v;
            *(uint2*)(g_xbf + (size_t)r*128 + lane*4) =
                make_uint2(packbf(v.x, v.y), packbf(v.z, v.w));
        }
    }
}

// ---------------- edge encoder: ea = ef[E,32] @ W[32,128] + b  (bf16 out) ---
__global__ void enc_edges_kernel(const float* __restrict__ ef,
                                 const float* __restrict__ W,
                                 const float* __restrict__ b) {
    extern __shared__ float sm[];
    float* sIn = sm;            // 64x32
    float* sW  = sm + 64*32;    // 32x128
    int tid = threadIdx.x, warp = tid >> 5, lane = tid & 31;
    size_t eb = (size_t)blockIdx.x * 64;
#pragma unroll
    for (int it = 0; it < 2; ++it) {
        int idx = tid + it*256;
        ((float4*)sIn)[idx] = ((const float4*)(ef + eb*32))[idx];
    }
#pragma unroll
    for (int it = 0; it < 4; ++it) {
        int idx = tid + it*256;
        ((float4*)sW)[idx] = ((const float4*)W)[idx];
    }
    __syncthreads();
    float acc[8][4];
#pragma unroll
    for (int i = 0; i < 8; ++i) { acc[i][0]=acc[i][1]=acc[i][2]=acc[i][3]=0.f; }
#pragma unroll 8
    for (int k = 0; k < 32; ++k) {
        float4 w = ((float4*)(sW + k*128))[lane];
#pragma unroll
        for (int i = 0; i < 8; ++i) {
            float a = sIn[(warp*8 + i)*32 + k];
            acc[i][0] = fmaf(a, w.x, acc[i][0]);
            acc[i][1] = fmaf(a, w.y, acc[i][1]);
            acc[i][2] = fmaf(a, w.z, acc[i][2]);
            acc[i][3] = fmaf(a, w.w, acc[i][3]);
        }
    }
    float4 bb = ((const float4*)b)[lane];
#pragma unroll
    for (int i = 0; i < 8; ++i) {
        size_t e = eb + warp*8 + i;
        *(uint2*)(g_ea + e*128 + lane*4) =
            make_uint2(packbf(acc[i][0]+bb.x, acc[i][1]+bb.y),
                       packbf(acc[i][2]+bb.z, acc[i][3]+bb.w));
    }
}

// --------- per-layer node precompute (mma): xa = x@W1a + cong*wc + b1 ; xb = x@W1b
__global__ void __launch_bounds__(256,2) node_pre_mma(const float* __restrict__ cong,
                                 const float* __restrict__ w1l,  // [385,128]
                                 const float* __restrict__ b1) {
    extern __shared__ __nv_bfloat16 smx[];
    __nv_bfloat16* sA = smx;
    __nv_bfloat16* sW = smx + 128*LDS;
    int tid = threadIdx.x, warp = tid >> 5, lane = tid & 31;
    int rb = blockIdx.x * 128;
#pragma unroll
    for (int it = 0; it < 8; ++it) {
        int idx = tid + it*256; int row = idx >> 4, c = idx & 15;
        int r = rb + row; if (r >= Nn) r = Nn - 1;
        *(uint4*)(sA + row*LDS + c*8) = __ldg((const uint4*)(g_xbf + (size_t)r*128) + c);
    }
    float acc[16][4];
#pragma unroll
    for (int j = 0; j < 16; ++j) { acc[j][0]=acc[j][1]=acc[j][2]=acc[j][3]=0.f; }
#pragma unroll 1
    for (int ph = 0; ph < 2; ++ph) {
        __syncthreads();
        load_w_split(w1l, sW, ph, tid);
        __syncthreads();
        mma_gemm128(sA, sW, acc, warp, lane);
    }
    int g = lane >> 2, t4 = lane & 3;
    int r0 = rb + warp*16 + g, r1 = r0 + 8;
    float c0 = cong[r0 < Nn ? r0 : Nn-1];
    float c1 = cong[r1 < Nn ? r1 : Nn-1];
#pragma unroll
    for (int j = 0; j < 16; ++j) {
        int col = j*8 + t4*2;
        float2 wc = *(const float2*)(w1l + 384*128 + col);
        float2 bb = *(const float2*)(b1 + col);
        if (r0 < Nn)
            *(unsigned*)(g_xa + (size_t)r0*128 + col) =
                packbf(acc[j][0] + c0*wc.x + bb.x, acc[j][1] + c0*wc.y + bb.y);
        if (r1 < Nn)
            *(unsigned*)(g_xa + (size_t)r1*128 + col) =
                packbf(acc[j][2] + c1*wc.x + bb.x, acc[j][3] + c1*wc.y + bb.y);
        acc[j][0]=acc[j][1]=acc[j][2]=acc[j][3]=0.f;
    }
#pragma unroll 1
    for (int ph = 0; ph < 2; ++ph) {
        __syncthreads();
        load_w_split(w1l + 128*128, sW, ph, tid);
        __syncthreads();
        mma_gemm128(sA, sW, acc, warp, lane);
    }
#pragma unroll
    for (int j = 0; j < 16; ++j) {
        int col = j*8 + t4*2;
        if (r0 < Nn)
            *(unsigned*)(g_xb + (size_t)r0*128 + col) = packbf(acc[j][0], acc[j][1]);
        if (r1 < Nn)
            *(unsigned*)(g_xb + (size_t)r1*128 + col) = packbf(acc[j][2], acc[j][3]);
    }
}

// ---------------- zero helpers ----------------------------------------------
__global__ void zero_agg_kernel() {
    size_t i = (size_t)blockIdx.x * blockDim.x + threadIdx.x;
    size_t n = (size_t)Nn * 128;
    if (i < n) g_agg[i] = 0.f;
}
__global__ void zero_red_kernel() { if (threadIdx.x < 128) g_red[threadIdx.x] = 0.f; }

// ------- edge kernel (mma): h1 = relu(ea@W1e + xa[src] + xb[dst]);
// ------- m = h1@W2 + b2; agg[dst] += m  -------------------------------------
__global__ void __launch_bounds__(256,2) edge_mma_kernel(const int* __restrict__ eidx,
                                const float* __restrict__ W1e,  // [128,128] fp32
                                const float* __restrict__ W2,   // [128,128] fp32
                                const float* __restrict__ b2) {
    extern __shared__ __nv_bfloat16 smx[];
    __nv_bfloat16* sA = smx;
    __nv_bfloat16* sW = smx + 128*LDS;
    __nv_bfloat16* sG = smx + 2*128*LDS;
    __shared__ int sSe[128], sDe[128];
    int tid = threadIdx.x, warp = tid >> 5, lane = tid & 31;
    size_t eb = (size_t)blockIdx.x * 128;

    if (tid < 128) {
        sSe[tid] = eidx[eb + tid];
        sDe[tid] = eidx[(size_t)Ee + eb + tid];
    }
#pragma unroll
    for (int it = 0; it < 8; ++it) {
        int idx = tid + it*256; int row = idx >> 4, c = idx & 15;
        *(uint4*)(sA + row*LDS + c*8) = __ldg((const uint4*)(g_ea + (eb+row)*128) + c);
    }
    float acc[16][4];
#pragma unroll
    for (int j = 0; j < 16; ++j) { acc[j][0]=acc[j][1]=acc[j][2]=acc[j][3]=0.f; }
#pragma unroll 1
    for (int ph = 0; ph < 2; ++ph) {
        __syncthreads();
        load_w_split(W1e, sW, ph, tid);
        __syncthreads();
        mma_gemm128(sA, sW, acc, warp, lane);
    }
    __syncthreads();
    // stage gathered xa[src] + xb[dst] into sG
#pragma unroll
    for (int it = 0; it < 8; ++it) {
        int idx = tid + it*256; int row = idx >> 4, c = idx & 15;
        uint4 a = __ldg((const uint4*)(g_xa + (size_t)sSe[row]*128) + c);
        uint4 b = __ldg((const uint4*)(g_xb + (size_t)sDe[row]*128) + c);
        uint4 r;
        ((__nv_bfloat162&)r.x) = __hadd2(((__nv_bfloat162&)a.x), ((__nv_bfloat162&)b.x));
        ((__nv_bfloat162&)r.y) = __hadd2(((__nv_bfloat162&)a.y), ((__nv_bfloat162&)b.y));
        ((__nv_bfloat162&)r.z) = __hadd2(((__nv_bfloat162&)a.z), ((__nv_bfloat162&)b.z));
        ((__nv_bfloat162&)r.w) = __hadd2(((__nv_bfloat162&)a.w), ((__nv_bfloat162&)b.w));
        *(uint4*)(sG + row*LDS + c*8) = r;
    }
    __syncthreads();
    int g = lane >> 2, t4 = lane & 3;
    // h1 = relu(acc + sG) -> sA (each warp touches only its own rows)
#pragma unroll
    for (int j = 0; j < 16; ++j) {
        int col = j*8 + t4*2;
#pragma unroll
        for (int rr = 0; rr < 2; ++rr) {
            int row = warp*16 + g + rr*8;
            float2 gv = unpackbf(*(unsigned*)(sG + row*LDS + col));
            float h0 = fmaxf(acc[j][2*rr]   + gv.x, 0.f);
            float h1 = fmaxf(acc[j][2*rr+1] + gv.y, 0.f);
            *(unsigned*)(sA + row*LDS + col) = packbf(h0, h1);
            acc[j][2*rr] = 0.f; acc[j][2*rr+1] = 0.f;
        }
    }
#pragma unroll 1
    for (int ph = 0; ph < 2; ++ph) {
        __syncthreads();
        load_w_split(W2, sW, ph, tid);
        __syncthreads();
        mma_gemm128(sA, sW, acc, warp, lane);
    }
    // epilogue: + b2, scatter-add into g_agg
#pragma unroll
    for (int j = 0; j < 16; ++j) {
        int col = j*8 + t4*2;
        float2 bb = *(const float2*)(b2 + col);
#pragma unroll
        for (int rr = 0; rr < 2; ++rr) {
            int row = warp*16 + g + rr*8;
            float* dp = g_agg + (size_t)sDe[row]*128 + col;
            atomicAdd(dp,     acc[j][2*rr]   + bb.x);
            atomicAdd(dp + 1, acc[j][2*rr+1] + bb.y);
        }
    }
}

// ------- update (mma): x = LN(x + MLP([x, agg])) ----------------------------
__global__ void __launch_bounds__(256,2) update_mma(const float* __restrict__ U1,  // [256,128]
                               const float* __restrict__ ub1,
                               const float* __restrict__ U2,  // [128,128]
                               const float* __restrict__ ub2,
                               const float* __restrict__ lw,
                               const float* __restrict__ lb) {
    extern __shared__ __nv_bfloat16 smx[];
    __nv_bfloat16* sA = smx;
    __nv_bfloat16* sW = smx + 128*LDS;
    int tid = threadIdx.x, warp = tid >> 5, lane = tid & 31;
    int rb = blockIdx.x * 128;
    float acc[16][4];
#pragma unroll
    for (int j = 0; j < 16; ++j) { acc[j][0]=acc[j][1]=acc[j][2]=acc[j][3]=0.f; }
#pragma unroll 1
    for (int kc = 0; kc < 2; ++kc) {
        __syncthreads();
        if (kc == 0) {
#pragma unroll
            for (int it = 0; it < 8; ++it) {
                int idx = tid + it*256; int row = idx >> 4, c = idx & 15;
                int r = rb + row; if (r >= Nn) r = Nn - 1;
                *(uint4*)(sA + row*LDS + c*8) =
                    __ldg((const uint4*)(g_xbf + (size_t)r*128) + c);
            }
        } else {
#pragma unroll
            for (int it = 0; it < 16; ++it) {
                int idx = tid + it*256; int row = idx >> 5, c4 = idx & 31;
                int r = rb + row; if (r >= Nn) r = Nn - 1;
                float4 w = __ldg((const float4*)(g_agg + (size_t)r*128) + c4);
                *(uint2*)(sA + row*LDS + c4*4) =
                    make_uint2(packbf(w.x, w.y), packbf(w.z, w.w));
            }
        }
#pragma unroll 1
        for (int ph = 0; ph < 2; ++ph) {
            __syncthreads();
            load_w_split(U1 + (size_t)kc*128*128, sW, ph, tid);
            __syncthreads();
            mma_gemm128(sA, sW, acc, warp, lane);
        }
    }
    __syncthreads();
    int g = lane >> 2, t4 = lane & 3;
    // h1 = relu(acc + ub1) -> sA
#pragma unroll
    for (int j = 0; j < 16; ++j) {
        int col = j*8 + t4*2;
        float2 bb = *(const float2*)(ub1 + col);
#pragma unroll
        for (int rr = 0; rr < 2; ++rr) {
            int row = warp*16 + g + rr*8;
            float h0 = fmaxf(acc[j][2*rr]   + bb.x, 0.f);
            float h1 = fmaxf(acc[j][2*rr+1] + bb.y, 0.f);
            *(unsigned*)(sA + row*LDS + col) = packbf(h0, h1);
            acc[j][2*rr] = 0.f; acc[j][2*rr+1] = 0.f;
        }
    }
#pragma unroll 1
    for (int ph = 0; ph < 2; ++ph) {
        __syncthreads();
        load_w_split(U2, sW, ph, tid);
        __syncthreads();
        mma_gemm128(sA, sW, acc, warp, lane);
    }
    // residual + bias, then LayerNorm per row
    int r0 = rb + warp*16 + g, r1 = r0 + 8;
    int r0c = r0 < Nn ? r0 : Nn-1, r1c = r1 < Nn ? r1 : Nn-1;
    float s0 = 0.f, s1 = 0.f;
#pragma unroll
    for (int j = 0; j < 16; ++j) {
        int col = j*8 + t4*2;
        float2 bb = *(const float2*)(ub2 + col);
        float2 x0 = *(const float2*)(g_x + (size_t)r0c*128 + col);
        float2 x1 = *(const float2*)(g_x + (size_t)r1c*128 + col);
        acc[j][0] += x0.x + bb.x;  acc[j][1] += x0.y + bb.y;
        acc[j][2] += x1.x + bb.x;  acc[j][3] += x1.y + bb.y;
        s0 += acc[j][0] + acc[j][1];
        s1 += acc[j][2] + acc[j][3];
    }
    s0 += __shfl_xor_sync(0xffffffffu, s0, 1);
    s0 += __shfl_xor_sync(0xffffffffu, s0, 2);
    s1 += __shfl_xor_sync(0xffffffffu, s1, 1);
    s1 += __shfl_xor_sync(0xffffffffu, s1, 2);
    float mu0 = s0 * (1.f/128.f), mu1 = s1 * (1.f/128.f);
    float q0 = 0.f, q1 = 0.f;
#pragma unroll
    for (int j = 0; j < 16; ++j) {
        float d0 = acc[j][0]-mu0, d1 = acc[j][1]-mu0;
        float d2 = acc[j][2]-mu1, d3 = acc[j][3]-mu1;
        q0 += d0*d0 + d1*d1;
        q1 += d2*d2 + d3*d3;
    }
    q0 += __shfl_xor_sync(0xffffffffu, q0, 1);
    q0 += __shfl_xor_sync(0xffffffffu, q0, 2);
    q1 += __shfl_xor_sync(0xffffffffu, q1, 1);
    q1 += __shfl_xor_sync(0xffffffffu, q1, 2);
    float rstd0 = rsqrtf(q0 * (1.f/128.f) + 1e-5f);
    float rstd1 = rsqrtf(q1 * (1.f/128.f) + 1e-5f);
#pragma unroll
    for (int j = 0; j < 16; ++j) {
        int col = j*8 + t4*2;
        float2 lw2 = *(const float2*)(lw + col);
        float2 lb2 = *(const float2*)(lb + col);
        if (r0 < Nn) {
            float o0 = (acc[j][0]-mu0)*rstd0*lw2.x + lb2.x;
            float o1 = (acc[j][1]-mu0)*rstd0*lw2.y + lb2.y;
            *(float2*)(g_x + (size_t)r0*128 + col) = make_float2(o0, o1);
            *(unsigned*)(g_xbf + (size_t)r0*128 + col) = packbf(o0, o1);
        }
        if (r1 < Nn) {
            float o2 = (acc[j][2]-mu1)*rstd1*lw2.x + lb2.x;
            float o3 = (acc[j][3]-mu1)*rstd1*lw2.y + lb2.y;
            *(float2*)(g_x + (size_t)r1*128 + col) = make_float2(o2, o3);
            *(unsigned*)(g_xbf + (size_t)r1*128 + col) = packbf(o2, o3);
        }
    }
}

// ---------------- column-sum reduce over nodes ------------------------------
__global__ void reduce_kernel() {
    int j = threadIdx.x;       // 128 threads
    int chunk = (Nn + gridDim.x - 1) / gridDim.x;
    int r0 = blockIdx.x * chunk;
    int r1 = r0 + chunk; if (r1 > Nn) r1 = Nn;
    float s = 0.f;
    for (int r = r0; r < r1; ++r) s += g_x[(size_t)r*128 + j];
    atomicAdd(&g_red[j], s);
}

// ---------------- readout head (single block, 128 threads) ------------------
__global__ void final_kernel(const void* __restrict__ maskp,
                             const float* __restrict__ uw1, const float* __restrict__ ub1f,
                             const float* __restrict__ uw2, const float* __restrict__ ub2f,
                             const float* __restrict__ rw1, const float* __restrict__ rb1,
                             const float* __restrict__ rw2, const float* __restrict__ rb2,
                             const float* __restrict__ rw3, const float* __restrict__ rb3,
                             float* __restrict__ out) {
    __shared__ float sge[128], s1[128], s2[128];
    __shared__ int c1s, c2s;
    __shared__ float sufs;
    int j = threadIdx.x;
    if (j == 0) { c1s = 0; c2s = 0; sufs = 0.f; }
    __syncthreads();
    const unsigned char* mb = (const unsigned char*)maskp;
    int c1 = 0, c2 = 0;
    for (int i = j; i < Nn; i += 128) {
        unsigned char v = mb[i];
        if (v) { if ((i & 3) == 0) c1++; else c2++; }
    }
    atomicAdd(&c1s, c1); atomicAdd(&c2s, c2);
    __syncthreads();
    float s = 0.f;
    if (c2s == 0) {
        const int* mi = (const int*)maskp;
        for (int i = j; i < Nn; i += 128) s += (mi[i] != 0) ? 1.f : 0.f;
    } else if (c1s == 0) {
        const float* mf = (const float*)maskp;
        for (int i = j; i < Nn; i += 128) s += mf[i];
    } else {
        for (int i = j; i < Nn; i += 128) s += mb[i] ? 1.f : 0.f;
    }
    atomicAdd(&sufs, s);
    sge[j] = g_red[j] * (1.f/(float)Nn);
    __syncthreads();
    float uf = sufs * (1.f/(float)Nn);
    s1[j] = fmaxf(uf * uw1[j] + ub1f[j], 0.f);
    __syncthreads();
    float t = ub2f[j];
    for (int k = 0; k < 128; ++k) t = fmaf(s1[k], uw2[k*128 + j], t);
    s2[j] = t;
    __syncthreads();
    float h = rb1[j];
    for (int k = 0; k < 128; ++k) h = fmaf(sge[k], rw1[k*128 + j], h);
    for (int k = 0; k < 128; ++k) h = fmaf(s2[k], rw1[(128 + k)*128 + j], h);
    s1[j] = fmaxf(h, 0.f);
    __syncthreads();
    if (j < 64) {
        float gv = rb2[j];
        for (int k = 0; k < 128; ++k) gv = fmaf(s1[k], rw2[k*64 + j], gv);
        s2[j] = fmaxf(gv, 0.f);
    }
    __syncthreads();
    if (j == 0) {
        float o = rb3[0];
        for (int k = 0; k < 64; ++k) o = fmaf(s2[k], rw3[k], o);
        out[0] = 1.f / (1.f + expf(-o));
    }
}

// ---------------- launch -----------------------------------------------------
extern "C" void kernel_launch(void* const* d_in, const int* in_sizes, int n_in,
                              void* d_out, int out_size) {
    const float* nf        = (const float*)d_in[0];
    const float* ef        = (const float*)d_in[1];
    const float* cong      = (const float*)d_in[2];
    const int*   eidx      = (const int*)d_in[3];
    const void*  mask      = d_in[4];
    const float* enc_node_w = (const float*)d_in[5];
    const float* enc_node_b = (const float*)d_in[6];
    const float* enc_edge_w = (const float*)d_in[7];
    const float* enc_edge_b = (const float*)d_in[8];
    const float* msg_w1 = (const float*)d_in[9];
    const float* msg_b1 = (const float*)d_in[10];
    const float* msg_w2 = (const float*)d_in[11];
    const float* msg_b2 = (const float*)d_in[12];
    const float* upd_w1 = (const float*)d_in[13];
    const float* upd_b1 = (const float*)d_in[14];
    const float* upd_w2 = (const float*)d_in[15];
    const float* upd_b2 = (const float*)d_in[16];
    const float* ln_w   = (const float*)d_in[17];
    const float* ln_b   = (const float*)d_in[18];
    const float* unr_w1 = (const float*)d_in[19];
    const float* unr_b1 = (const float*)d_in[20];
    const float* unr_w2 = (const float*)d_in[21];
    const float* unr_b2 = (const float*)d_in[22];
    const float* ro_w1  = (const float*)d_in[23];
    const float* ro_b1  = (const float*)d_in[24];
    const float* ro_w2  = (const float*)d_in[25];
    const float* ro_b2  = (const float*)d_in[26];
    const float* ro_w3  = (const float*)d_in[27];
    const float* ro_b3  = (const float*)d_in[28];
    float* out = (float*)d_out;

    const int SM_ENC_N = (64*64 + 64*128) * 4;     // 48 KB
    const int SM_ENC_E = (64*32 + 32*128) * 4;     // 24 KB
    const int SM_MMA2  = 2 * 128 * LDS * 2;        // 69632 B (sA + sW)
    const int SM_MMA3  = 3 * 128 * LDS * 2;        // 104448 B (sA + sW + sG)

    cudaFuncSetAttribute(enc_nodes_kernel, cudaFuncAttributeMaxDynamicSharedMemorySize, SM_ENC_N);
    cudaFuncSetAttribute(node_pre_mma,     cudaFuncAttributeMaxDynamicSharedMemorySize, SM_MMA2);
    cudaFuncSetAttribute(edge_mma_kernel,  cudaFuncAttributeMaxDynamicSharedMemorySize, SM_MMA3);
    cudaFuncSetAttribute(update_mma,       cudaFuncAttributeMaxDynamicSharedMemorySize, SM_MMA2);

    const int ENC_N_BLOCKS = (Nn + 63) / 64;     // 782
    const int ENC_E_BLOCKS = Ee / 64;            // 12500
    const int NODE_BLOCKS  = (Nn + 127) / 128;   // 391
    const int EDGE_BLOCKS  = Ee / 128;           // 6250

    enc_nodes_kernel<<<ENC_N_BLOCKS, 256, SM_ENC_N>>>(nf, enc_node_w, enc_node_b);
    enc_edges_kernel<<<ENC_E_BLOCKS, 256, SM_ENC_E>>>(ef, enc_edge_w, enc_edge_b);

    for (int l = 0; l < 4; ++l) {
        node_pre_mma<<<NODE_BLOCKS, 256, SM_MMA2>>>(
            cong, msg_w1 + (size_t)l*385*128, msg_b1 + (size_t)l*128);
        zero_agg_kernel<<<(Nn*128 + 1023)/1024, 1024>>>();
        edge_mma_kernel<<<EDGE_BLOCKS, 256, SM_MMA3>>>(
            eidx,
            msg_w1 + ((size_t)l*385 + 256)*128,
            msg_w2 + (size_t)l*128*128,
            msg_b2 + (size_t)l*128);
        update_mma<<<NODE_BLOCKS, 256, SM_MMA2>>>(
            upd_w1 + (size_t)l*256*128, upd_b1 + (size_t)l*128,
            upd_w2 + (size_t)l*128*128, upd_b2 + (size_t)l*128,
            ln_w + (size_t)l*128, ln_b + (size_t)l*128);
    }

    zero_red_kernel<<<1, 128>>>();
    reduce_kernel<<<250, 128>>>();
    final_kernel<<<1, 128>>>(mask, unr_w1, unr_b1, unr_w2, unr_b2,
                             ro_w1, ro_b1, ro_w2, ro_b2, ro_w3, ro_b3, out);
}

// round 4
// speedup vs baseline: 2.5253x; 1.4442x over previous
#include <cuda_runtime.h>
#include <cuda_bf16.h>
#include <math.h>

#define Nn 50000
#define Ee 800000
#define LDS 136       // smem row stride (bf16 elems) for 128-wide tiles
#define LDSE 40       // smem row stride for 32-wide ef tiles (conflict-free)
#define B_EL 16384    // 128*128
#define WL   229376   // per-layer elems in g_w (14 * B_EL)
#define EW_OFF ((size_t)4*WL)

// ---------------- scratch (device globals; no allocation allowed) -----------
__device__ float          g_x  [(size_t)Nn*128];
__device__ __nv_bfloat16  g_xbf[(size_t)Nn*128];
__device__ __nv_bfloat16  g_xa [(size_t)Nn*128];
__device__ __nv_bfloat16  g_xb [(size_t)Nn*128];
__device__ float          g_agg[(size_t)Nn*128];
__device__ __nv_bfloat16  g_ea [(size_t)Ee*128];
__device__ float          g_red[128];
// pre-split weights: per layer [W1a_h][W1a_l][W1b_h][W1b_l][W1e_h][W1e_l]
// [W2_h][W2_l][U1_h(2B)][U1_l(2B)][U2_h][U2_l]; then enc_edge hi/lo (4096 ea)
__device__ __nv_bfloat16  g_w[(size_t)4*WL + 8192];

// ---------------- mma helpers ------------------------------------------------
__device__ __forceinline__ unsigned sptr(const void* p){
    return (unsigned)__cvta_generic_to_shared((void*)p);
}
__device__ __forceinline__ void ldsmA(unsigned a, unsigned &r0, unsigned &r1,
                                      unsigned &r2, unsigned &r3){
    asm volatile("ldmatrix.sync.aligned.m8n8.x4.shared.b16 {%0,%1,%2,%3},[%4];"
        : "=r"(r0),"=r"(r1),"=r"(r2),"=r"(r3) : "r"(a));
}
__device__ __forceinline__ void ldsmBT(unsigned a, unsigned &r0, unsigned &r1,
                                       unsigned &r2, unsigned &r3){
    asm volatile("ldmatrix.sync.aligned.m8n8.x4.trans.shared.b16 {%0,%1,%2,%3},[%4];"
        : "=r"(r0),"=r"(r1),"=r"(r2),"=r"(r3) : "r"(a));
}
__device__ __forceinline__ void mma_bf16(float* c, unsigned a0, unsigned a1,
                                         unsigned a2, unsigned a3,
                                         unsigned b0, unsigned b1){
    asm volatile("mma.sync.aligned.m16n8k16.row.col.f32.bf16.bf16.f32 "
        "{%0,%1,%2,%3},{%4,%5,%6,%7},{%8,%9},{%0,%1,%2,%3};"
        : "+f"(c[0]),"+f"(c[1]),"+f"(c[2]),"+f"(c[3])
        : "r"(a0),"r"(a1),"r"(a2),"r"(a3),"r"(b0),"r"(b1));
}
__device__ __forceinline__ unsigned packbf(float a, float b){
    __nv_bfloat162 h = __floats2bfloat162_rn(a, b);
    return *(unsigned*)&h;
}
__device__ __forceinline__ float2 unpackbf(unsigned u){
    __nv_bfloat162 h = *(__nv_bfloat162*)&u;
    return make_float2(__bfloat162float(h.x), __bfloat162float(h.y));
}

// ---------------- weight pre-split: hi=bf16(w), lo=bf16(w-hi) ----------------
__global__ void split_kernel(const float* __restrict__ src, size_t dstoff, int n){
    int i = blockIdx.x*blockDim.x + threadIdx.x;
    if (i < n){
        float w = src[i];
        __nv_bfloat16 h = __float2bfloat16(w);
        g_w[dstoff + i] = h;
        g_w[dstoff + n + i] = __float2bfloat16(w - __bfloat162float(h));
    }
}

// Load dense bf16 [128][128] weight into SMEM [128][LDS].  256 threads.
__device__ __forceinline__ void load_wbf(const __nv_bfloat16* __restrict__ Wd,
                                         __nv_bfloat16* sW, int tid){
#pragma unroll
    for (int it = 0; it < 8; ++it){
        int idx = tid + it*256;               // 2048 uint4
        int row = idx >> 4, c = idx & 15;
        *(uint4*)(sW + row*LDS + c*8) = __ldg((const uint4*)Wd + idx);
    }
}

// Warp-level 16x128 @ 128x128 mma accumulate. Warp w owns rows w*16..w*16+15.
__device__ __forceinline__ void mma_gemm128(const __nv_bfloat16* sA,
                                            const __nv_bfloat16* sW,
                                            float acc[16][4], int warp, int lane){
    unsigned aB = sptr(sA + (warp*16 + (lane & 15))*LDS + (lane >> 4)*8);
    unsigned bB = sptr(sW + (lane & 15)*LDS + (lane >> 4)*8);
#pragma unroll
    for (int kk = 0; kk < 8; ++kk){
        unsigned a0,a1,a2,a3;
        ldsmA(aB + kk*32, a0,a1,a2,a3);
#pragma unroll
        for (int jp = 0; jp < 8; ++jp){
            unsigned b0,b1,b2,b3;
            ldsmBT(bB + kk*(16*LDS*2) + jp*32, b0,b1,b2,b3);
            mma_bf16(acc[2*jp],   a0,a1,a2,a3, b0,b1);
            mma_bf16(acc[2*jp+1], a0,a1,a2,a3, b2,b3);
        }
    }
}

// ---------------- node encoder: x = nf[N,64] @ W[64,128] + b (fp32 FFMA) ----
__global__ void enc_nodes_kernel(const float* __restrict__ nf,
                                 const float* __restrict__ W,
                                 const float* __restrict__ b) {
    extern __shared__ float sm[];
    float* sIn = sm;            // 64x64
    float* sW  = sm + 64*64;    // 64x128
    int tid = threadIdx.x, warp = tid >> 5, lane = tid & 31;
    int rb = blockIdx.x * 64;
#pragma unroll
    for (int it = 0; it < 4; ++it) {
        int idx = tid + it*256;
        int row = idx >> 4, c4 = idx & 15;
        int r = rb + row; if (r >= Nn) r = Nn - 1;
        ((float4*)sIn)[idx] = ((const float4*)(nf + (size_t)r*64))[c4];
    }
#pragma unroll
    for (int it = 0; it < 8; ++it) {
        int idx = tid + it*256;
        ((float4*)sW)[idx] = ((const float4*)W)[idx];
    }
    __syncthreads();
    float acc[8][4];
#pragma unroll
    for (int i = 0; i < 8; ++i) { acc[i][0]=acc[i][1]=acc[i][2]=acc[i][3]=0.f; }
#pragma unroll 8
    for (int k = 0; k < 64; ++k) {
        float4 w = ((float4*)(sW + k*128))[lane];
#pragma unroll
        for (int i = 0; i < 8; ++i) {
            float a = sIn[(warp*8 + i)*64 + k];
            acc[i][0] = fmaf(a, w.x, acc[i][0]);
            acc[i][1] = fmaf(a, w.y, acc[i][1]);
            acc[i][2] = fmaf(a, w.z, acc[i][2]);
            acc[i][3] = fmaf(a, w.w, acc[i][3]);
        }
    }
    float4 bb = ((const float4*)b)[lane];
#pragma unroll
    for (int i = 0; i < 8; ++i) {
        int r = rb + warp*8 + i;
        if (r < Nn) {
            float4 v = make_float4(acc[i][0]+bb.x, acc[i][1]+bb.y,
                                   acc[i][2]+bb.z, acc[i][3]+bb.w);
            ((float4*)(g_x + (size_t)r*128))[lane] = v;
            *(uint2*)(g_xbf + (size_t)r*128 + lane*4) =
                make_uint2(packbf(v.x, v.y), packbf(v.z, v.w));
        }
    }
}

// ------- edge encoder (mma): ea = ef[E,32] @ W[32,128] + b  (bf16 out) ------
__global__ void __launch_bounds__(256,4) enc_edges_mma(const float* __restrict__ ef,
                                                       const float* __restrict__ b) {
    extern __shared__ __nv_bfloat16 smx[];
    __nv_bfloat16* sA = smx;                    // 128 x LDSE (ef bf16)
    __nv_bfloat16* sW = smx + 128*LDSE;         // 64 x LDS  (hi 32 rows + lo 32 rows)
    int tid = threadIdx.x, warp = tid >> 5, lane = tid & 31;
    size_t eb = (size_t)blockIdx.x * 128;
    // load ef tile (fp32 -> bf16)
#pragma unroll
    for (int it = 0; it < 4; ++it) {
        int idx = tid + it*256;                 // 1024 float4
        int row = idx >> 3, c4 = idx & 7;
        float4 w = __ldg((const float4*)(ef + (eb + row)*32) + c4);
        *(uint2*)(sA + row*LDSE + c4*4) = make_uint2(packbf(w.x, w.y), packbf(w.z, w.w));
    }
    // load pre-split weights: 64 rows x 16 uint4
#pragma unroll
    for (int it = 0; it < 4; ++it) {
        int idx = tid + it*256;                 // 1024 uint4
        int row = idx >> 4, c = idx & 15;
        *(uint4*)(sW + row*LDS + c*8) = __ldg((const uint4*)(g_w + EW_OFF) + idx);
    }
    __syncthreads();
    float acc[16][4];
#pragma unroll
    for (int j = 0; j < 16; ++j) { acc[j][0]=acc[j][1]=acc[j][2]=acc[j][3]=0.f; }
    unsigned aB = sptr(sA + (warp*16 + (lane & 15))*LDSE + (lane >> 4)*8);
#pragma unroll
    for (int part = 0; part < 2; ++part) {
        unsigned bB = sptr(sW + (part*32 + (lane & 15))*LDS + (lane >> 4)*8);
#pragma unroll
        for (int kk = 0; kk < 2; ++kk) {
            unsigned a0,a1,a2,a3;
            ldsmA(aB + kk*32, a0,a1,a2,a3);
#pragma unroll
            for (int jp = 0; jp < 8; ++jp) {
                unsigned b0,b1,b2,b3;
                ldsmBT(bB + kk*(16*LDS*2) + jp*32, b0,b1,b2,b3);
                mma_bf16(acc[2*jp],   a0,a1,a2,a3, b0,b1);
                mma_bf16(acc[2*jp+1], a0,a1,a2,a3, b2,b3);
            }
        }
    }
    int g = lane >> 2, t4 = lane & 3;
    size_t r0 = eb + warp*16 + g, r1 = r0 + 8;
#pragma unroll
    for (int j = 0; j < 16; ++j) {
        int col = j*8 + t4*2;
        float2 bb = *(const float2*)(b + col);
        *(unsigned*)(g_ea + r0*128 + col) = packbf(acc[j][0]+bb.x, acc[j][1]+bb.y);
        *(unsigned*)(g_ea + r1*128 + col) = packbf(acc[j][2]+bb.x, acc[j][3]+bb.y);
    }
}

// --------- per-layer node precompute (mma): xa = x@W1a + cong*wc + b1 ; xb = x@W1b
__global__ void __launch_bounds__(256,2) node_pre_mma(const float* __restrict__ cong,
                                 const float* __restrict__ w1l,  // [385,128] fp32 (row 384 + b via args)
                                 const float* __restrict__ b1,
                                 int layer) {
    extern __shared__ __nv_bfloat16 smx[];
    __nv_bfloat16* sA = smx;
    __nv_bfloat16* sW = smx + 128*LDS;
    const __nv_bfloat16* wb = g_w + (size_t)layer*WL;
    int tid = threadIdx.x, warp = tid >> 5, lane = tid & 31;
    int rb = blockIdx.x * 128;
#pragma unroll
    for (int it = 0; it < 8; ++it) {
        int idx = tid + it*256; int row = idx >> 4, c = idx & 15;
        int r = rb + row; if (r >= Nn) r = Nn - 1;
        *(uint4*)(sA + row*LDS + c*8) = __ldg((const uint4*)(g_xbf + (size_t)r*128) + c);
    }
    float acc[16][4];
#pragma unroll
    for (int j = 0; j < 16; ++j) { acc[j][0]=acc[j][1]=acc[j][2]=acc[j][3]=0.f; }
#pragma unroll 1
    for (int ph = 0; ph < 2; ++ph) {
        __syncthreads();
        load_wbf(wb + (size_t)ph*B_EL, sW, tid);     // W1a hi / lo
        __syncthreads();
        mma_gemm128(sA, sW, acc, warp, lane);
    }
    int g = lane >> 2, t4 = lane & 3;
    int r0 = rb + warp*16 + g, r1 = r0 + 8;
    float c0 = cong[r0 < Nn ? r0 : Nn-1];
    float c1 = cong[r1 < Nn ? r1 : Nn-1];
#pragma unroll
    for (int j = 0; j < 16; ++j) {
        int col = j*8 + t4*2;
        float2 wc = *(const float2*)(w1l + 384*128 + col);
        float2 bb = *(const float2*)(b1 + col);
        if (r0 < Nn)
            *(unsigned*)(g_xa + (size_t)r0*128 + col) =
                packbf(acc[j][0] + c0*wc.x + bb.x, acc[j][1] + c0*wc.y + bb.y);
        if (r1 < Nn)
            *(unsigned*)(g_xa + (size_t)r1*128 + col) =
                packbf(acc[j][2] + c1*wc.x + bb.x, acc[j][3] + c1*wc.y + bb.y);
        acc[j][0]=acc[j][1]=acc[j][2]=acc[j][3]=0.f;
    }
#pragma unroll 1
    for (int ph = 0; ph < 2; ++ph) {
        __syncthreads();
        load_wbf(wb + (size_t)(2+ph)*B_EL, sW, tid); // W1b hi / lo
        __syncthreads();
        mma_gemm128(sA, sW, acc, warp, lane);
    }
#pragma unroll
    for (int j = 0; j < 16; ++j) {
        int col = j*8 + t4*2;
        if (r0 < Nn)
            *(unsigned*)(g_xb + (size_t)r0*128 + col) = packbf(acc[j][0], acc[j][1]);
        if (r1 < Nn)
            *(unsigned*)(g_xb + (size_t)r1*128 + col) = packbf(acc[j][2], acc[j][3]);
    }
}

// ---------------- zero helpers ----------------------------------------------
__global__ void zero_agg_kernel() {
    size_t i = (size_t)blockIdx.x * blockDim.x + threadIdx.x;
    size_t n = (size_t)Nn * 128;
    if (i < n) g_agg[i] = 0.f;
}
__global__ void zero_red_kernel() { if (threadIdx.x < 128) g_red[threadIdx.x] = 0.f; }

// ------- persistent edge kernel: weights resident, grid-stride over tiles ---
// h1 = relu(ea@W1e + xa[src] + xb[dst]); m = h1@W2 + b2; agg[dst] += m.
// All per-tile SMEM is warp-local => only __syncwarp in the loop.
__global__ void __launch_bounds__(256,1) edge_persist_kernel(
                                const int* __restrict__ eidx,
                                const float* __restrict__ b2,
                                int layer) {
    extern __shared__ __nv_bfloat16 smx[];
    __nv_bfloat16* sA  = smx;                 // 128 x LDS (ea, then h1)
    __nv_bfloat16* sG  = smx + 128*LDS;       // 128 x LDS (gather)
    __nv_bfloat16* sW0 = smx + 2*128*LDS;     // W1e hi
    __nv_bfloat16* sW1 = smx + 3*128*LDS;     // W1e lo
    __nv_bfloat16* sW2 = smx + 4*128*LDS;     // W2 hi
    __nv_bfloat16* sW3 = smx + 5*128*LDS;     // W2 lo
    __shared__ int sSe[128], sDe[128];
    int tid = threadIdx.x, warp = tid >> 5, lane = tid & 31;
    const __nv_bfloat16* wb = g_w + (size_t)layer*WL;

    load_wbf(wb + 4*B_EL, sW0, tid);
    load_wbf(wb + 5*B_EL, sW1, tid);
    load_wbf(wb + 6*B_EL, sW2, tid);
    load_wbf(wb + 7*B_EL, sW3, tid);
    __syncthreads();

    int g = lane >> 2, t4 = lane & 3;
    float2 bb[16];
#pragma unroll
    for (int j = 0; j < 16; ++j) bb[j] = *(const float2*)(b2 + j*8 + t4*2);

    for (int t = blockIdx.x; t < Ee/128; t += gridDim.x) {
        size_t eb = (size_t)t * 128;
        __syncwarp();   // prev tile's GEMM2 reads of sA/sG/indices complete
        if (lane < 16) {
            sSe[warp*16 + lane] = eidx[eb + warp*16 + lane];
            sDe[warp*16 + lane] = eidx[(size_t)Ee + eb + warp*16 + lane];
        }
#pragma unroll
        for (int i = 0; i < 8; ++i) {        // own 16 rows of ea
            int idx = i*32 + lane; int row = idx >> 4, c = idx & 15;
            *(uint4*)(sA + (warp*16+row)*LDS + c*8) =
                __ldg((const uint4*)(g_ea + (eb + warp*16 + row)*128) + c);
        }
        __syncwarp();   // indices + ea visible within warp
#pragma unroll
        for (int i = 0; i < 8; ++i) {        // gather own 16 rows
            int idx = i*32 + lane; int row = idx >> 4, c = idx & 15;
            int rs = sSe[warp*16 + row], rd = sDe[warp*16 + row];
            uint4 a = __ldg((const uint4*)(g_xa + (size_t)rs*128) + c);
            uint4 b = __ldg((const uint4*)(g_xb + (size_t)rd*128) + c);
            uint4 r;
            ((__nv_bfloat162&)r.x) = __hadd2(((__nv_bfloat162&)a.x), ((__nv_bfloat162&)b.x));
            ((__nv_bfloat162&)r.y) = __hadd2(((__nv_bfloat162&)a.y), ((__nv_bfloat162&)b.y));
            ((__nv_bfloat162&)r.z) = __hadd2(((__nv_bfloat162&)a.z), ((__nv_bfloat162&)b.z));
            ((__nv_bfloat162&)r.w) = __hadd2(((__nv_bfloat162&)a.w), ((__nv_bfloat162&)b.w));
            *(uint4*)(sG + (warp*16+row)*LDS + c*8) = r;
        }
        __syncwarp();   // sG visible
        float acc[16][4];
#pragma unroll
        for (int j = 0; j < 16; ++j) { acc[j][0]=acc[j][1]=acc[j][2]=acc[j][3]=0.f; }
        mma_gemm128(sA, sW0, acc, warp, lane);
        mma_gemm128(sA, sW1, acc, warp, lane);
        __syncwarp();   // all lanes done reading ea from sA
#pragma unroll
        for (int j = 0; j < 16; ++j) {
            int col = j*8 + t4*2;
#pragma unroll
            for (int rr = 0; rr < 2; ++rr) {
                int row = warp*16 + g + rr*8;
                float2 gv = unpackbf(*(unsigned*)(sG + row*LDS + col));
                float h0 = fmaxf(acc[j][2*rr]   + gv.x, 0.f);
                float h1 = fmaxf(acc[j][2*rr+1] + gv.y, 0.f);
                *(unsigned*)(sA + row*LDS + col) = packbf(h0, h1);
                acc[j][2*rr] = 0.f; acc[j][2*rr+1] = 0.f;
            }
        }
        __syncwarp();   // h1 visible
        mma_gemm128(sA, sW2, acc, warp, lane);
        mma_gemm128(sA, sW3, acc, warp, lane);
#pragma unroll
        for (int j = 0; j < 16; ++j) {
            int col = j*8 + t4*2;
#pragma unroll
            for (int rr = 0; rr < 2; ++rr) {
                int row = warp*16 + g + rr*8;
                float* dp = g_agg + (size_t)sDe[row]*128 + col;
                atomicAdd(dp,     acc[j][2*rr]   + bb[j].x);
                atomicAdd(dp + 1, acc[j][2*rr+1] + bb[j].y);
            }
        }
    }
}

// ------- update (mma): x = LN(x + MLP([x, agg])) ----------------------------
__global__ void __launch_bounds__(256,2) update_mma(const float* __restrict__ ub1,
                               const float* __restrict__ ub2,
                               const float* __restrict__ lw,
                               const float* __restrict__ lb,
                               int layer) {
    extern __shared__ __nv_bfloat16 smx[];
    __nv_bfloat16* sA = smx;
    __nv_bfloat16* sW = smx + 128*LDS;
    const __nv_bfloat16* wb = g_w + (size_t)layer*WL;
    int tid = threadIdx.x, warp = tid >> 5, lane = tid & 31;
    int rb = blockIdx.x * 128;
    float acc[16][4];
#pragma unroll
    for (int j = 0; j < 16; ++j) { acc[j][0]=acc[j][1]=acc[j][2]=acc[j][3]=0.f; }
#pragma unroll 1
    for (int kc = 0; kc < 2; ++kc) {
        __syncthreads();
        if (kc == 0) {
#pragma unroll
            for (int it = 0; it < 8; ++it) {
                int idx = tid + it*256; int row = idx >> 4, c = idx & 15;
                int r = rb + row; if (r >= Nn) r = Nn - 1;
                *(uint4*)(sA + row*LDS + c*8) =
                    __ldg((const uint4*)(g_xbf + (size_t)r*128) + c);
            }
        } else {
#pragma unroll
            for (int it = 0; it < 16; ++it) {
                int idx = tid + it*256; int row = idx >> 5, c4 = idx & 31;
                int r = rb + row; if (r >= Nn) r = Nn - 1;
                float4 w = __ldg((const float4*)(g_agg + (size_t)r*128) + c4);
                *(uint2*)(sA + row*LDS + c4*4) =
                    make_uint2(packbf(w.x, w.y), packbf(w.z, w.w));
            }
        }
#pragma unroll 1
        for (int ph = 0; ph < 2; ++ph) {
            __syncthreads();
            // U1 hi block at 8B (2B long), lo at 10B; chunk kc within each
            load_wbf(wb + (size_t)(8 + ph*2 + kc)*B_EL, sW, tid);
            __syncthreads();
            mma_gemm128(sA, sW, acc, warp, lane);
        }
    }
    __syncthreads();
    int g = lane >> 2, t4 = lane & 3;
#pragma unroll
    for (int j = 0; j < 16; ++j) {
        int col = j*8 + t4*2;
        float2 bb = *(const float2*)(ub1 + col);
#pragma unroll
        for (int rr = 0; rr < 2; ++rr) {
            int row = warp*16 + g + rr*8;
            float h0 = fmaxf(acc[j][2*rr]   + bb.x, 0.f);
            float h1 = fmaxf(acc[j][2*rr+1] + bb.y, 0.f);
            *(unsigned*)(sA + row*LDS + col) = packbf(h0, h1);
            acc[j][2*rr] = 0.f; acc[j][2*rr+1] = 0.f;
        }
    }
#pragma unroll 1
    for (int ph = 0; ph < 2; ++ph) {
        __syncthreads();
        load_wbf(wb + (size_t)(12 + ph)*B_EL, sW, tid);  // U2 hi / lo
        __syncthreads();
        mma_gemm128(sA, sW, acc, warp, lane);
    }
    // residual + bias, then LayerNorm per row
    int r0 = rb + warp*16 + g, r1 = r0 + 8;
    int r0c = r0 < Nn ? r0 : Nn-1, r1c = r1 < Nn ? r1 : Nn-1;
    float s0 = 0.f, s1 = 0.f;
#pragma unroll
    for (int j = 0; j < 16; ++j) {
        int col = j*8 + t4*2;
        float2 bb = *(const float2*)(ub2 + col);
        float2 x0 = *(const float2*)(g_x + (size_t)r0c*128 + col);
        float2 x1 = *(const float2*)(g_x + (size_t)r1c*128 + col);
        acc[j][0] += x0.x + bb.x;  acc[j][1] += x0.y + bb.y;
        acc[j][2] += x1.x + bb.x;  acc[j][3] += x1.y + bb.y;
        s0 += acc[j][0] + acc[j][1];
        s1 += acc[j][2] + acc[j][3];
    }
    s0 += __shfl_xor_sync(0xffffffffu, s0, 1);
    s0 += __shfl_xor_sync(0xffffffffu, s0, 2);
    s1 += __shfl_xor_sync(0xffffffffu, s1, 1);
    s1 += __shfl_xor_sync(0xffffffffu, s1, 2);
    float mu0 = s0 * (1.f/128.f), mu1 = s1 * (1.f/128.f);
    float q0 = 0.f, q1 = 0.f;
#pragma unroll
    for (int j = 0; j < 16; ++j) {
        float d0 = acc[j][0]-mu0, d1 = acc[j][1]-mu0;
        float d2 = acc[j][2]-mu1, d3 = acc[j][3]-mu1;
        q0 += d0*d0 + d1*d1;
        q1 += d2*d2 + d3*d3;
    }
    q0 += __shfl_xor_sync(0xffffffffu, q0, 1);
    q0 += __shfl_xor_sync(0xffffffffu, q0, 2);
    q1 += __shfl_xor_sync(0xffffffffu, q1, 1);
    q1 += __shfl_xor_sync(0xffffffffu, q1, 2);
    float rstd0 = rsqrtf(q0 * (1.f/128.f) + 1e-5f);
    float rstd1 = rsqrtf(q1 * (1.f/128.f) + 1e-5f);
#pragma unroll
    for (int j = 0; j < 16; ++j) {
        int col = j*8 + t4*2;
        float2 lw2 = *(const float2*)(lw + col);
        float2 lb2 = *(const float2*)(lb + col);
        if (r0 < Nn) {
            float o0 = (acc[j][0]-mu0)*rstd0*lw2.x + lb2.x;
            float o1 = (acc[j][1]-mu0)*rstd0*lw2.y + lb2.y;
            *(float2*)(g_x + (size_t)r0*128 + col) = make_float2(o0, o1);
            *(unsigned*)(g_xbf + (size_t)r0*128 + col) = packbf(o0, o1);
        }
        if (r1 < Nn) {
            float o2 = (acc[j][2]-mu1)*rstd1*lw2.x + lb2.x;
            float o3 = (acc[j][3]-mu1)*rstd1*lw2.y + lb2.y;
            *(float2*)(g_x + (size_t)r1*128 + col) = make_float2(o2, o3);
            *(unsigned*)(g_xbf + (size_t)r1*128 + col) = packbf(o2, o3);
        }
    }
}

// ---------------- column-sum reduce over nodes ------------------------------
__global__ void reduce_kernel() {
    int j = threadIdx.x;       // 128 threads
    int chunk = (Nn + gridDim.x - 1) / gridDim.x;
    int r0 = blockIdx.x * chunk;
    int r1 = r0 + chunk; if (r1 > Nn) r1 = Nn;
    float s = 0.f;
    for (int r = r0; r < r1; ++r) s += g_x[(size_t)r*128 + j];
    atomicAdd(&g_red[j], s);
}

// ---------------- readout head (single block, 128 threads) ------------------
__global__ void final_kernel(const void* __restrict__ maskp,
                             const float* __restrict__ uw1, const float* __restrict__ ub1f,
                             const float* __restrict__ uw2, const float* __restrict__ ub2f,
                             const float* __restrict__ rw1, const float* __restrict__ rb1,
                             const float* __restrict__ rw2, const float* __restrict__ rb2,
                             const float* __restrict__ rw3, const float* __restrict__ rb3,
                             float* __restrict__ out) {
    __shared__ float sge[128], s1[128], s2[128];
    __shared__ int c1s, c2s;
    __shared__ float sufs;
    int j = threadIdx.x;
    if (j == 0) { c1s = 0; c2s = 0; sufs = 0.f; }
    __syncthreads();
    const unsigned char* mb = (const unsigned char*)maskp;
    int c1 = 0, c2 = 0;
    for (int i = j; i < Nn; i += 128) {
        unsigned char v = mb[i];
        if (v) { if ((i & 3) == 0) c1++; else c2++; }
    }
    atomicAdd(&c1s, c1); atomicAdd(&c2s, c2);
    __syncthreads();
    float s = 0.f;
    if (c2s == 0) {
        const int* mi = (const int*)maskp;
        for (int i = j; i < Nn; i += 128) s += (mi[i] != 0) ? 1.f : 0.f;
    } else if (c1s == 0) {
        const float* mf = (const float*)maskp;
        for (int i = j; i < Nn; i += 128) s += mf[i];
    } else {
        for (int i = j; i < Nn; i += 128) s += mb[i] ? 1.f : 0.f;
    }
    atomicAdd(&sufs, s);
    sge[j] = g_red[j] * (1.f/(float)Nn);
    __syncthreads();
    float uf = sufs * (1.f/(float)Nn);
    s1[j] = fmaxf(uf * uw1[j] + ub1f[j], 0.f);
    __syncthreads();
    float t = ub2f[j];
    for (int k = 0; k < 128; ++k) t = fmaf(s1[k], uw2[k*128 + j], t);
    s2[j] = t;
    __syncthreads();
    float h = rb1[j];
    for (int k = 0; k < 128; ++k) h = fmaf(sge[k], rw1[k*128 + j], h);
    for (int k = 0; k < 128; ++k) h = fmaf(s2[k], rw1[(128 + k)*128 + j], h);
    s1[j] = fmaxf(h, 0.f);
    __syncthreads();
    if (j < 64) {
        float gv = rb2[j];
        for (int k = 0; k < 128; ++k) gv = fmaf(s1[k], rw2[k*64 + j], gv);
        s2[j] = fmaxf(gv, 0.f);
    }
    __syncthreads();
    if (j == 0) {
        float o = rb3[0];
        for (int k = 0; k < 64; ++k) o = fmaf(s2[k], rw3[k], o);
        out[0] = 1.f / (1.f + expf(-o));
    }
}

// ---------------- launch -----------------------------------------------------
extern "C" void kernel_launch(void* const* d_in, const int* in_sizes, int n_in,
                              void* d_out, int out_size) {
    const float* nf        = (const float*)d_in[0];
    const float* ef        = (const float*)d_in[1];
    const float* cong      = (const float*)d_in[2];
    const int*   eidx      = (const int*)d_in[3];
    const void*  mask      = d_in[4];
    const float* enc_node_w = (const float*)d_in[5];
    const float* enc_node_b = (const float*)d_in[6];
    const float* enc_edge_w = (const float*)d_in[7];
    const float* enc_edge_b = (const float*)d_in[8];
    const float* msg_w1 = (const float*)d_in[9];
    const float* msg_b1 = (const float*)d_in[10];
    const float* msg_w2 = (const float*)d_in[11];
    const float* msg_b2 = (const float*)d_in[12];
    const float* upd_w1 = (const float*)d_in[13];
    const float* upd_b1 = (const float*)d_in[14];
    const float* upd_w2 = (const float*)d_in[15];
    const float* upd_b2 = (const float*)d_in[16];
    const float* ln_w   = (const float*)d_in[17];
    const float* ln_b   = (const float*)d_in[18];
    const float* unr_w1 = (const float*)d_in[19];
    const float* unr_b1 = (const float*)d_in[20];
    const float* unr_w2 = (const float*)d_in[21];
    const float* unr_b2 = (const float*)d_in[22];
    const float* ro_w1  = (const float*)d_in[23];
    const float* ro_b1  = (const float*)d_in[24];
    const float* ro_w2  = (const float*)d_in[25];
    const float* ro_b2  = (const float*)d_in[26];
    const float* ro_w3  = (const float*)d_in[27];
    const float* ro_b3  = (const float*)d_in[28];
    float* out = (float*)d_out;

    const int SM_ENC_N = (64*64 + 64*128) * 4;          // 48 KB
    const int SM_ENC_E = (128*LDSE + 64*LDS) * 2;       // ~27.6 KB
    const int SM_MMA2  = 2 * 128 * LDS * 2;             // 69632 B (sA + sW)
    const int SM_EDGEP = 6 * 128 * LDS * 2;             // 208896 B

    cudaFuncSetAttribute(enc_nodes_kernel,    cudaFuncAttributeMaxDynamicSharedMemorySize, SM_ENC_N);
    cudaFuncSetAttribute(enc_edges_mma,       cudaFuncAttributeMaxDynamicSharedMemorySize, SM_ENC_E);
    cudaFuncSetAttribute(node_pre_mma,        cudaFuncAttributeMaxDynamicSharedMemorySize, SM_MMA2);
    cudaFuncSetAttribute(edge_persist_kernel, cudaFuncAttributeMaxDynamicSharedMemorySize, SM_EDGEP);
    cudaFuncSetAttribute(update_mma,          cudaFuncAttributeMaxDynamicSharedMemorySize, SM_MMA2);

    // ---- pre-split all weights into g_w (bf16 hi/lo) ----
    for (int l = 0; l < 4; ++l) {
        size_t base = (size_t)l * WL;
        const float* w1 = msg_w1 + (size_t)l*385*128;
        split_kernel<<<64, 256>>>(w1,                 base + 0*B_EL, B_EL);   // W1a
        split_kernel<<<64, 256>>>(w1 + B_EL,          base + 2*B_EL, B_EL);   // W1b
        split_kernel<<<64, 256>>>(w1 + 2*B_EL,        base + 4*B_EL, B_EL);   // W1e
        split_kernel<<<64, 256>>>(msg_w2 + (size_t)l*B_EL,   base + 6*B_EL, B_EL);   // W2
        split_kernel<<<128,256>>>(upd_w1 + (size_t)l*2*B_EL, base + 8*B_EL, 2*B_EL); // U1
        split_kernel<<<64, 256>>>(upd_w2 + (size_t)l*B_EL,   base + 12*B_EL, B_EL);  // U2
    }
    split_kernel<<<16, 256>>>(enc_edge_w, EW_OFF, 4096);

    const int ENC_N_BLOCKS = (Nn + 63) / 64;     // 782
    const int NODE_BLOCKS  = (Nn + 127) / 128;   // 391
    const int ENC_E_BLOCKS = Ee / 128;           // 6250

    enc_nodes_kernel<<<ENC_N_BLOCKS, 256, SM_ENC_N>>>(nf, enc_node_w, enc_node_b);
    enc_edges_mma<<<ENC_E_BLOCKS, 256, SM_ENC_E>>>(ef, enc_edge_b);

    for (int l = 0; l < 4; ++l) {
        node_pre_mma<<<NODE_BLOCKS, 256, SM_MMA2>>>(
            cong, msg_w1 + (size_t)l*385*128, msg_b1 + (size_t)l*128, l);
        zero_agg_kernel<<<(Nn*128 + 1023)/1024, 1024>>>();
        edge_persist_kernel<<<148, 256, SM_EDGEP>>>(
            eidx, msg_b2 + (size_t)l*128, l);
        update_mma<<<NODE_BLOCKS, 256, SM_MMA2>>>(
            upd_b1 + (size_t)l*128, upd_b2 + (size_t)l*128,
            ln_w + (size_t)l*128, ln_b + (size_t)l*128, l);
    }

    zero_red_kernel<<<1, 128>>>();
    reduce_kernel<<<250, 128>>>();
    final_kernel<<<1, 128>>>(mask, unr_w1, unr_b1, unr_w2, unr_b2,
                             ro_w1, ro_b1, ro_w2, ro_b2, ro_w3, ro_b3, out);
}